// round 4
// baseline (speedup 1.0000x reference)
#include <cuda_runtime.h>

// Apply 4x4 gate U to wires {5,13} of a 26-wire (dim-2) state vector.
// Target address bits: 20 (wire 5, MSB of t) and 12 (wire 13, LSB of t).
// REST = 2^24, processed as 2^22 float4-groups per butterfly leg.
//
// R4 change vs R3: 2 float4-groups per thread with all 8 loads front-batched
// before any store — longer same-direction DRAM bursts to cut read/write
// turnaround loss. Groups are blockDim apart so every access stays
// warp-coalesced. Occupancy will drop (~70 regs) but R2/R3 proved occupancy
// is not binding here.

#define REST_COUNT (1u << 24)

__global__ __launch_bounds__(256)
void unitary_gate_kernel(const float* __restrict__ x,
                         const float* __restrict__ U,
                         float* __restrict__ y)
{
    // Each block covers 2*blockDim float4-groups.
    unsigned g0 = blockIdx.x * (blockDim.x * 2) + threadIdx.x;  // group id 0
    unsigned g1 = g0 + blockDim.x;                              // group id 1

    const float4* __restrict__ x4 = (const float4*)x;
    float4* __restrict__ y4 = (float4*)y;

    // group id -> element base address with zeros inserted at bits 12, 20
    unsigned rA = g0 << 2;
    unsigned rB = g1 << 2;
    unsigned baseA = (rA & 0xFFFu) | ((rA & 0x7F000u) << 1) | ((rA >> 19) << 21);
    unsigned baseB = (rB & 0xFFFu) | ((rB & 0x7F000u) << 1) | ((rB >> 19) << 21);

    unsigned iA0 = baseA >> 2;
    unsigned iA1 = (baseA + (1u << 12)) >> 2;
    unsigned iA2 = (baseA + (1u << 20)) >> 2;
    unsigned iA3 = (baseA + (1u << 20) + (1u << 12)) >> 2;
    unsigned iB0 = baseB >> 2;
    unsigned iB1 = (baseB + (1u << 12)) >> 2;
    unsigned iB2 = (baseB + (1u << 20)) >> 2;
    unsigned iB3 = (baseB + (1u << 20) + (1u << 12)) >> 2;

    // Front-batch all 8 loads (long read burst, MLP_p1 = 8).
    float4 aA0 = x4[iA0];
    float4 aA1 = x4[iA1];
    float4 aA2 = x4[iA2];
    float4 aA3 = x4[iA3];
    float4 aB0 = x4[iB0];
    float4 aB1 = x4[iB1];
    float4 aB2 = x4[iB2];
    float4 aB3 = x4[iB3];

    float u[16];
#pragma unroll
    for (int k = 0; k < 16; ++k) u[k] = __ldg(U + k);

    // Group A compute + stores (batched 4).
    float4 o0, o1, o2, o3;
    o0.x = u[0]*aA0.x + u[1]*aA1.x + u[2]*aA2.x + u[3]*aA3.x;
    o0.y = u[0]*aA0.y + u[1]*aA1.y + u[2]*aA2.y + u[3]*aA3.y;
    o0.z = u[0]*aA0.z + u[1]*aA1.z + u[2]*aA2.z + u[3]*aA3.z;
    o0.w = u[0]*aA0.w + u[1]*aA1.w + u[2]*aA2.w + u[3]*aA3.w;
    o1.x = u[4]*aA0.x + u[5]*aA1.x + u[6]*aA2.x + u[7]*aA3.x;
    o1.y = u[4]*aA0.y + u[5]*aA1.y + u[6]*aA2.y + u[7]*aA3.y;
    o1.z = u[4]*aA0.z + u[5]*aA1.z + u[6]*aA2.z + u[7]*aA3.z;
    o1.w = u[4]*aA0.w + u[5]*aA1.w + u[6]*aA2.w + u[7]*aA3.w;
    o2.x = u[8]*aA0.x + u[9]*aA1.x + u[10]*aA2.x + u[11]*aA3.x;
    o2.y = u[8]*aA0.y + u[9]*aA1.y + u[10]*aA2.y + u[11]*aA3.y;
    o2.z = u[8]*aA0.z + u[9]*aA1.z + u[10]*aA2.z + u[11]*aA3.z;
    o2.w = u[8]*aA0.w + u[9]*aA1.w + u[10]*aA2.w + u[11]*aA3.w;
    o3.x = u[12]*aA0.x + u[13]*aA1.x + u[14]*aA2.x + u[15]*aA3.x;
    o3.y = u[12]*aA0.y + u[13]*aA1.y + u[14]*aA2.y + u[15]*aA3.y;
    o3.z = u[12]*aA0.z + u[13]*aA1.z + u[14]*aA2.z + u[15]*aA3.z;
    o3.w = u[12]*aA0.w + u[13]*aA1.w + u[14]*aA2.w + u[15]*aA3.w;

    y4[iA0] = o0;
    y4[iA1] = o1;
    y4[iA2] = o2;
    y4[iA3] = o3;

    // Group B compute + stores (batched 4).
    o0.x = u[0]*aB0.x + u[1]*aB1.x + u[2]*aB2.x + u[3]*aB3.x;
    o0.y = u[0]*aB0.y + u[1]*aB1.y + u[2]*aB2.y + u[3]*aB3.y;
    o0.z = u[0]*aB0.z + u[1]*aB1.z + u[2]*aB2.z + u[3]*aB3.z;
    o0.w = u[0]*aB0.w + u[1]*aB1.w + u[2]*aB2.w + u[3]*aB3.w;
    o1.x = u[4]*aB0.x + u[5]*aB1.x + u[6]*aB2.x + u[7]*aB3.x;
    o1.y = u[4]*aB0.y + u[5]*aB1.y + u[6]*aB2.y + u[7]*aB3.y;
    o1.z = u[4]*aB0.z + u[5]*aB1.z + u[6]*aB2.z + u[7]*aB3.z;
    o1.w = u[4]*aB0.w + u[5]*aB1.w + u[6]*aB2.w + u[7]*aB3.w;
    o2.x = u[8]*aB0.x + u[9]*aB1.x + u[10]*aB2.x + u[11]*aB3.x;
    o2.y = u[8]*aB0.y + u[9]*aB1.y + u[10]*aB2.y + u[11]*aB3.y;
    o2.z = u[8]*aB0.z + u[9]*aB1.z + u[10]*aB2.z + u[11]*aB3.z;
    o2.w = u[8]*aB0.w + u[9]*aB1.w + u[10]*aB2.w + u[11]*aB3.w;
    o3.x = u[12]*aB0.x + u[13]*aB1.x + u[14]*aB2.x + u[15]*aB3.x;
    o3.y = u[12]*aB0.y + u[13]*aB1.y + u[14]*aB2.y + u[15]*aB3.y;
    o3.z = u[12]*aB0.z + u[13]*aB1.z + u[14]*aB2.z + u[15]*aB3.z;
    o3.w = u[12]*aB0.w + u[13]*aB1.w + u[14]*aB2.w + u[15]*aB3.w;

    y4[iB0] = o0;
    y4[iB1] = o1;
    y4[iB2] = o2;
    y4[iB3] = o3;
}

extern "C" void kernel_launch(void* const* d_in, const int* in_sizes, int n_in,
                              void* d_out, int out_size)
{
    const float* x = (const float*)d_in[0];
    const float* U = (const float*)d_in[1];
    float* y = (float*)d_out;

    unsigned threads = 256;
    unsigned total_groups = REST_COUNT / 4;          // 2^22 float4-groups
    unsigned blocks = total_groups / (threads * 2);  // 8192

    unitary_gate_kernel<<<blocks, threads>>>(x, U, y);
}

// round 6
// speedup vs baseline: 1.0098x; 1.0098x over previous
#include <cuda_runtime.h>

// Apply 4x4 gate U to wires {5,13} of a 26-wire (dim-2) state vector.
// Target address bits: 20 (wire 5, MSB of t) and 12 (wire 13, LSB of t).
// REST = 2^24; each thread handles 4 consecutive rest indices (float4) on
// each of the 4 butterfly legs -> fully coalesced 16B accesses.
//
// FINAL (R5 = best-measured R1 config, locked):
//  - default caching (streaming .cs hints measured -3% BW)
//  - no extra launch-bounds cap (occupancy 50->63% measured irrelevant)
//  - 1 float4-group per thread (2x unroll measured slightly worse)
// Measured: ~6450 GB/s HBM (81% DRAM), device time ~75us vs 64us
// theoretical floor for the irreducible 512 MB of traffic.

#define REST_COUNT (1u << 24)

__global__ __launch_bounds__(256)
void unitary_gate_kernel(const float* __restrict__ x,
                         const float* __restrict__ U,
                         float* __restrict__ y)
{
    unsigned tid = blockIdx.x * blockDim.x + threadIdx.x;   // 0 .. 2^22-1
    unsigned r = tid << 2;                                  // rest index (x4)

    // Insert zero bits at positions 12 and 20.
    unsigned base = (r & 0xFFFu) | ((r & 0x7F000u) << 1) | ((r >> 19) << 21);

    const float4* __restrict__ x4 = (const float4*)x;
    float4* __restrict__ y4 = (float4*)y;

    unsigned i0 = base >> 2;                              // t=0
    unsigned i1 = (base + (1u << 12)) >> 2;               // t=1
    unsigned i2 = (base + (1u << 20)) >> 2;               // t=2
    unsigned i3 = (base + (1u << 20) + (1u << 12)) >> 2;  // t=3

    float4 a0 = x4[i0];
    float4 a1 = x4[i1];
    float4 a2 = x4[i2];
    float4 a3 = x4[i3];

    // U broadcasts via L1 (uniform across threads).
    float u[16];
#pragma unroll
    for (int k = 0; k < 16; ++k) u[k] = __ldg(U + k);

    float4 o0, o1, o2, o3;
    o0.x = u[0]*a0.x + u[1]*a1.x + u[2]*a2.x + u[3]*a3.x;
    o0.y = u[0]*a0.y + u[1]*a1.y + u[2]*a2.y + u[3]*a3.y;
    o0.z = u[0]*a0.z + u[1]*a1.z + u[2]*a2.z + u[3]*a3.z;
    o0.w = u[0]*a0.w + u[1]*a1.w + u[2]*a2.w + u[3]*a3.w;

    o1.x = u[4]*a0.x + u[5]*a1.x + u[6]*a2.x + u[7]*a3.x;
    o1.y = u[4]*a0.y + u[5]*a1.y + u[6]*a2.y + u[7]*a3.y;
    o1.z = u[4]*a0.z + u[5]*a1.z + u[6]*a2.z + u[7]*a3.z;
    o1.w = u[4]*a0.w + u[5]*a1.w + u[6]*a2.w + u[7]*a3.w;

    o2.x = u[8]*a0.x + u[9]*a1.x + u[10]*a2.x + u[11]*a3.x;
    o2.y = u[8]*a0.y + u[9]*a1.y + u[10]*a2.y + u[11]*a3.y;
    o2.z = u[8]*a0.z + u[9]*a1.z + u[10]*a2.z + u[11]*a3.z;
    o2.w = u[8]*a0.w + u[9]*a1.w + u[10]*a2.w + u[11]*a3.w;

    o3.x = u[12]*a0.x + u[13]*a1.x + u[14]*a2.x + u[15]*a3.x;
    o3.y = u[12]*a0.y + u[13]*a1.y + u[14]*a2.y + u[15]*a3.y;
    o3.z = u[12]*a0.z + u[13]*a1.z + u[14]*a2.z + u[15]*a3.z;
    o3.w = u[12]*a0.w + u[13]*a1.w + u[14]*a2.w + u[15]*a3.w;

    y4[i0] = o0;
    y4[i1] = o1;
    y4[i2] = o2;
    y4[i3] = o3;
}

extern "C" void kernel_launch(void* const* d_in, const int* in_sizes, int n_in,
                              void* d_out, int out_size)
{
    const float* x = (const float*)d_in[0];
    const float* U = (const float*)d_in[1];
    float* y = (float*)d_out;

    unsigned threads = 256;
    unsigned total_threads = REST_COUNT / 4;   // 2^22
    unsigned blocks = total_threads / threads; // 16384

    unitary_gate_kernel<<<blocks, threads>>>(x, U, y);
}